// round 2
// baseline (speedup 1.0000x reference)
#include <cuda_runtime.h>
#include <cstdint>

// ---------------------------------------------------------------------------
// Problem constants
// ---------------------------------------------------------------------------
#define BB 8
#define TT 1024
#define CC 1024
#define HH 16
#define DD 64
#define NTOK (BB * TT)           // 8192
#define SCALE_ATTN 0.07216878364870323f  // 1/sqrt(3*C/H) = 1/sqrt(192)

// ---------------------------------------------------------------------------
// Scratch (device globals; no dynamic allocation allowed)
// ---------------------------------------------------------------------------
__device__ float g_h[NTOK * CC];          // ln1 out          32 MB
__device__ float g_qkv[NTOK * 3 * CC];    // qkv              96 MB
__device__ float g_y[NTOK * CC];          // attn out         32 MB
__device__ float g_h2[NTOK * CC];         // ln2 out          32 MB
__device__ float g_mid[NTOK * 4 * CC];    // mlp hidden      128 MB

// ---------------------------------------------------------------------------
// LayerNorm: one block per row, 256 threads, C=1024 (4 floats/thread)
// ---------------------------------------------------------------------------
__global__ __launch_bounds__(256)
void ln_kernel(const float* __restrict__ x, const float* __restrict__ g,
               const float* __restrict__ b, float* __restrict__ out) {
    __shared__ float rs[8];
    __shared__ float rq[8];
    const int row = blockIdx.x;
    const float* xr = x + (size_t)row * CC;
    float* yr = out + (size_t)row * CC;
    const int c = threadIdx.x * 4;

    float4 v = *(const float4*)(xr + c);
    float s  = v.x + v.y + v.z + v.w;
    float sq = v.x * v.x + v.y * v.y + v.z * v.z + v.w * v.w;
    #pragma unroll
    for (int o = 16; o; o >>= 1) {
        s  += __shfl_xor_sync(0xffffffffu, s, o);
        sq += __shfl_xor_sync(0xffffffffu, sq, o);
    }
    if ((threadIdx.x & 31) == 0) {
        rs[threadIdx.x >> 5] = s;
        rq[threadIdx.x >> 5] = sq;
    }
    __syncthreads();
    s = 0.f; sq = 0.f;
    #pragma unroll
    for (int i = 0; i < 8; i++) { s += rs[i]; sq += rq[i]; }

    const float mean = s * (1.f / CC);
    const float var  = sq * (1.f / CC) - mean * mean;
    const float rstd = rsqrtf(var + 1e-5f);

    float4 g4 = *(const float4*)(g + c);
    float4 b4 = *(const float4*)(b + c);
    float4 o;
    o.x = (v.x - mean) * rstd * g4.x + b4.x;
    o.y = (v.y - mean) * rstd * g4.y + b4.y;
    o.z = (v.z - mean) * rstd * g4.z + b4.z;
    o.w = (v.w - mean) * rstd * g4.w + b4.w;
    *(float4*)(yr + c) = o;
}

// ---------------------------------------------------------------------------
// SGEMM: C[M,N] = A[M,K] @ B[K,N] + bias (+ residual) (or ReLU)
// 128x128 tile, k-step 8, 256 threads, 8x8 per-thread micro-tile.
// EPI: 0 = bias, 1 = bias + residual add, 2 = bias + relu
// ---------------------------------------------------------------------------
template <int EPI>
__global__ __launch_bounds__(256, 2)
void sgemm_kernel(const float* __restrict__ A, const float* __restrict__ B,
                  const float* __restrict__ bias, const float* __restrict__ Res,
                  float* __restrict__ C, int M, int N, int K) {
    __shared__ __align__(16) float As[8][128];   // A^T tile: As[k][m]
    __shared__ __align__(16) float Bs[8][128];   // Bs[k][n]

    const int tid = threadIdx.x;
    const int tx = tid & 15;          // n sub-tile
    const int ty = tid >> 4;          // m sub-tile
    const int m0 = blockIdx.y * 128;
    const int n0 = blockIdx.x * 128;

    // A tile load map: 128 rows x 8 k, float4 -> 256 loads
    const int arow = tid >> 1;
    const int acol = (tid & 1) << 2;
    // B tile load map: 8 k x 128 n, float4 -> 256 loads
    const int brow = tid >> 5;
    const int bcol = (tid & 31) << 2;

    const float* Aptr = A + (size_t)(m0 + arow) * K + acol;
    const float* Bptr = B + (size_t)brow * N + n0 + bcol;

    float acc[8][8];
    #pragma unroll
    for (int i = 0; i < 8; i++)
        #pragma unroll
        for (int j = 0; j < 8; j++) acc[i][j] = 0.f;

    for (int k0 = 0; k0 < K; k0 += 8) {
        float4 a4 = *(const float4*)(Aptr + k0);
        float4 b4 = *(const float4*)(Bptr + (size_t)k0 * N);
        As[acol + 0][arow] = a4.x;
        As[acol + 1][arow] = a4.y;
        As[acol + 2][arow] = a4.z;
        As[acol + 3][arow] = a4.w;
        *(float4*)&Bs[brow][bcol] = b4;
        __syncthreads();

        #pragma unroll
        for (int k = 0; k < 8; k++) {
            float a[8], b[8];
            *(float4*)(a)     = *(const float4*)&As[k][ty * 8];
            *(float4*)(a + 4) = *(const float4*)&As[k][ty * 8 + 4];
            *(float4*)(b)     = *(const float4*)&Bs[k][tx * 8];
            *(float4*)(b + 4) = *(const float4*)&Bs[k][tx * 8 + 4];
            #pragma unroll
            for (int i = 0; i < 8; i++)
                #pragma unroll
                for (int j = 0; j < 8; j++)
                    acc[i][j] = fmaf(a[i], b[j], acc[i][j]);
        }
        __syncthreads();
    }

    #pragma unroll
    for (int i = 0; i < 8; i++) {
        const int m = m0 + ty * 8 + i;
        const size_t rowoff = (size_t)m * N;
        #pragma unroll
        for (int j = 0; j < 8; j += 4) {
            const int n = n0 + tx * 8 + j;
            float4 bb = *(const float4*)(bias + n);
            float4 o;
            o.x = acc[i][j + 0] + bb.x;
            o.y = acc[i][j + 1] + bb.y;
            o.z = acc[i][j + 2] + bb.z;
            o.w = acc[i][j + 3] + bb.w;
            if (EPI == 1) {
                float4 r4 = *(const float4*)(Res + rowoff + n);
                o.x += r4.x; o.y += r4.y; o.z += r4.z; o.w += r4.w;
            }
            if (EPI == 2) {
                o.x = fmaxf(o.x, 0.f); o.y = fmaxf(o.y, 0.f);
                o.z = fmaxf(o.z, 0.f); o.w = fmaxf(o.w, 0.f);
            }
            *(float4*)(C + rowoff + n) = o;
        }
    }
}

// ---------------------------------------------------------------------------
// Causal flash attention, fp32. Block = (q-tile 64, head, batch), 256 thr.
// Per thread: 4x4 of the 64x64 S tile and 4x4 of the 64x64 O tile.
// Qs/Ks stored transposed ([d][token]) for conflict-free LDS.128 in S;
// P written transposed into the K buffer for conflict-free O-update reads.
// Total static smem = 3 * 16 KB = 48 KB.
// ---------------------------------------------------------------------------
__global__ __launch_bounds__(256)
void attn_kernel(const float* __restrict__ qkv, float* __restrict__ y) {
    __shared__ __align__(16) float Qs[64][64];   // Q^T, pre-scaled
    __shared__ __align__(16) float KPs[64][64];  // K^T, then P^T
    __shared__ __align__(16) float Vs[64][64];   // V natural [c][d]

    const int tid = threadIdx.x;
    const int qb = blockIdx.x;    // q tile (0..15)
    const int h  = blockIdx.y;    // head
    const int b  = blockIdx.z;    // batch
    const int rg = tid >> 4;      // row group: rows 4*rg .. +3
    const int cg = tid & 15;      // col group: cols 4*cg .. +3

    const size_t base = (size_t)b * TT * (3 * CC) + (size_t)h * DD;

    // --- load Q tile (transposed, pre-scaled) ---
    for (int i4 = tid; i4 < 1024; i4 += 256) {
        const int r = i4 >> 4;
        const int d0 = (i4 & 15) << 2;
        float4 q4 = *(const float4*)(qkv + base + (size_t)(qb * 64 + r) * (3 * CC) + d0);
        Qs[d0 + 0][r] = q4.x * SCALE_ATTN;
        Qs[d0 + 1][r] = q4.y * SCALE_ATTN;
        Qs[d0 + 2][r] = q4.z * SCALE_ATTN;
        Qs[d0 + 3][r] = q4.w * SCALE_ATTN;
    }

    float m[4], l[4], acc[4][4];
    #pragma unroll
    for (int i = 0; i < 4; i++) {
        m[i] = -1e30f; l[i] = 0.f;
        #pragma unroll
        for (int j = 0; j < 4; j++) acc[i][j] = 0.f;
    }

    for (int kb = 0; kb <= qb; kb++) {
        __syncthreads();   // protect KPs/Vs from previous iteration readers
        // --- load K^T and V tiles ---
        for (int i4 = tid; i4 < 1024; i4 += 256) {
            const int c = i4 >> 4;
            const int d0 = (i4 & 15) << 2;
            const size_t kaddr = base + CC + (size_t)(kb * 64 + c) * (3 * CC) + d0;
            float4 k4 = *(const float4*)(qkv + kaddr);
            KPs[d0 + 0][c] = k4.x;
            KPs[d0 + 1][c] = k4.y;
            KPs[d0 + 2][c] = k4.z;
            KPs[d0 + 3][c] = k4.w;
            float4 v4 = *(const float4*)(qkv + kaddr + CC);
            *(float4*)&Vs[c][d0] = v4;
        }
        __syncthreads();

        // --- S = Q K^T (4x4 per thread) ---
        float s[4][4];
        #pragma unroll
        for (int i = 0; i < 4; i++)
            #pragma unroll
            for (int j = 0; j < 4; j++) s[i][j] = 0.f;

        #pragma unroll 8
        for (int d = 0; d < 64; d++) {
            float qa[4], kk[4];
            *(float4*)qa = *(const float4*)&Qs[d][rg << 2];
            *(float4*)kk = *(const float4*)&KPs[d][cg << 2];
            #pragma unroll
            for (int i = 0; i < 4; i++)
                #pragma unroll
                for (int j = 0; j < 4; j++)
                    s[i][j] = fmaf(qa[i], kk[j], s[i][j]);
        }

        // --- causal mask (diagonal tile only) ---
        if (kb == qb) {
            #pragma unroll
            for (int i = 0; i < 4; i++)
                #pragma unroll
                for (int j = 0; j < 4; j++)
                    if ((cg << 2) + j > (rg << 2) + i) s[i][j] = -1e30f;
        }

        // --- online softmax update ---
        float rmax[4], rsum[4], corr[4];
        #pragma unroll
        for (int i = 0; i < 4; i++) {
            rmax[i] = fmaxf(fmaxf(s[i][0], s[i][1]), fmaxf(s[i][2], s[i][3]));
        }
        #pragma unroll
        for (int o = 1; o < 16; o <<= 1)
            #pragma unroll
            for (int i = 0; i < 4; i++)
                rmax[i] = fmaxf(rmax[i], __shfl_xor_sync(0xffffffffu, rmax[i], o));
        #pragma unroll
        for (int i = 0; i < 4; i++) {
            const float mn = fmaxf(m[i], rmax[i]);
            corr[i] = __expf(m[i] - mn);
            m[i] = mn;
            rsum[i] = 0.f;
            #pragma unroll
            for (int j = 0; j < 4; j++) {
                s[i][j] = __expf(s[i][j] - mn);
                rsum[i] += s[i][j];
            }
        }
        #pragma unroll
        for (int o = 1; o < 16; o <<= 1)
            #pragma unroll
            for (int i = 0; i < 4; i++)
                rsum[i] += __shfl_xor_sync(0xffffffffu, rsum[i], o);
        #pragma unroll
        for (int i = 0; i < 4; i++) {
            l[i] = l[i] * corr[i] + rsum[i];
            #pragma unroll
            for (int j = 0; j < 4; j++) acc[i][j] *= corr[i];
        }

        __syncthreads();   // done reading KPs as K^T
        // --- write P^T into KPs: Pt[c][r] ---
        #pragma unroll
        for (int j = 0; j < 4; j++) {
            const int c = (cg << 2) + j;
            *(float4*)&KPs[c][rg << 2] = make_float4(s[0][j], s[1][j], s[2][j], s[3][j]);
        }
        __syncthreads();

        // --- O += P @ V ---
        #pragma unroll 8
        for (int c = 0; c < 64; c++) {
            float p[4], vv[4];
            *(float4*)p  = *(const float4*)&KPs[c][rg << 2];
            *(float4*)vv = *(const float4*)&Vs[c][cg << 2];
            #pragma unroll
            for (int i = 0; i < 4; i++)
                #pragma unroll
                for (int j = 0; j < 4; j++)
                    acc[i][j] = fmaf(p[i], vv[j], acc[i][j]);
        }
    }

    // --- finalize and write y in [B, T, H*D] layout ---
    #pragma unroll
    for (int i = 0; i < 4; i++) {
        const float inv = 1.f / l[i];
        const int r = (rg << 2) + i;
        const size_t off = ((size_t)(b * TT + qb * 64 + r)) * CC + h * DD + (cg << 2);
        float4 o = make_float4(acc[i][0] * inv, acc[i][1] * inv,
                               acc[i][2] * inv, acc[i][3] * inv);
        *(float4*)(y + off) = o;
    }
}

// ---------------------------------------------------------------------------
// Launch
// ---------------------------------------------------------------------------
extern "C" void kernel_launch(void* const* d_in, const int* in_sizes, int n_in,
                              void* d_out, int out_size) {
    const float* x     = (const float*)d_in[0];
    const float* Wqkv  = (const float*)d_in[1];
    const float* bqkv  = (const float*)d_in[2];
    const float* Wproj = (const float*)d_in[3];
    const float* bproj = (const float*)d_in[4];
    const float* ln1_g = (const float*)d_in[5];
    const float* ln1_b = (const float*)d_in[6];
    const float* ln2_g = (const float*)d_in[7];
    const float* ln2_b = (const float*)d_in[8];
    const float* W1    = (const float*)d_in[9];
    const float* b1    = (const float*)d_in[10];
    const float* W2    = (const float*)d_in[11];
    const float* b2    = (const float*)d_in[12];
    float* out = (float*)d_out;

    float *h, *qkv, *y, *h2, *mid;
    cudaGetSymbolAddress((void**)&h,   g_h);
    cudaGetSymbolAddress((void**)&qkv, g_qkv);
    cudaGetSymbolAddress((void**)&y,   g_y);
    cudaGetSymbolAddress((void**)&h2,  g_h2);
    cudaGetSymbolAddress((void**)&mid, g_mid);

    // 1. h = ln1(x)
    ln_kernel<<<NTOK, 256>>>(x, ln1_g, ln1_b, h);
    // 2. qkv = h @ Wqkv + bqkv
    sgemm_kernel<0><<<dim3(3 * CC / 128, NTOK / 128), 256>>>(
        h, Wqkv, bqkv, nullptr, qkv, NTOK, 3 * CC, CC);
    // 3. y = causal_attention(qkv)
    attn_kernel<<<dim3(TT / 64, HH, BB), 256>>>(qkv, y);
    // 4. out = x + y @ Wproj + bproj    (x1 lives in d_out)
    sgemm_kernel<1><<<dim3(CC / 128, NTOK / 128), 256>>>(
        y, Wproj, bproj, x, out, NTOK, CC, CC);
    // 5. h2 = ln2(x1)
    ln_kernel<<<NTOK, 256>>>(out, ln2_g, ln2_b, h2);
    // 6. mid = relu(h2 @ W1 + b1)
    sgemm_kernel<2><<<dim3(4 * CC / 128, NTOK / 128), 256>>>(
        h2, W1, b1, nullptr, mid, NTOK, 4 * CC, CC);
    // 7. out = x1 + mid @ W2 + b2   (in-place residual on d_out)
    sgemm_kernel<1><<<dim3(CC / 128, NTOK / 128), 256>>>(
        mid, W2, b2, out, out, NTOK, CC, 4 * CC);
}

// round 3
// speedup vs baseline: 2.3294x; 2.3294x over previous
#include <cuda_runtime.h>
#include <cstdint>

// ---------------------------------------------------------------------------
// Problem constants
// ---------------------------------------------------------------------------
#define BB 8
#define TT 1024
#define CC 1024
#define HH 16
#define DD 64
#define NTOK (BB * TT)           // 8192
#define SCALE_ATTN 0.07216878364870323f  // 1/sqrt(3*C/H) = 1/sqrt(192)

// ---------------------------------------------------------------------------
// Scratch (device globals; no dynamic allocation allowed)
// ---------------------------------------------------------------------------
__device__ float g_h[NTOK * CC];          // ln1 out          32 MB
__device__ float g_qkv[NTOK * 3 * CC];    // qkv              96 MB
__device__ float g_y[NTOK * CC];          // attn out         32 MB
__device__ float g_h2[NTOK * CC];         // ln2 out          32 MB
__device__ float g_mid[NTOK * 4 * CC];    // mlp hidden      128 MB

// ---------------------------------------------------------------------------
// Helpers
// ---------------------------------------------------------------------------
__device__ __forceinline__ uint32_t f2tf32(float f) {
    uint32_t u;
    asm("cvt.rna.tf32.f32 %0, %1;" : "=r"(u) : "f"(f));
    return u;
}

__device__ __forceinline__ void mma_tf32(float* c, const uint32_t* a, const uint32_t* b) {
    asm volatile(
        "mma.sync.aligned.m16n8k8.row.col.f32.tf32.tf32.f32 "
        "{%0,%1,%2,%3}, {%4,%5,%6,%7}, {%8,%9}, {%0,%1,%2,%3};"
        : "+f"(c[0]), "+f"(c[1]), "+f"(c[2]), "+f"(c[3])
        : "r"(a[0]), "r"(a[1]), "r"(a[2]), "r"(a[3]), "r"(b[0]), "r"(b[1]));
}

__device__ __forceinline__ void cp_async16(void* smem_ptr, const void* gptr) {
    uint32_t sp = (uint32_t)__cvta_generic_to_shared(smem_ptr);
    asm volatile("cp.async.ca.shared.global [%0], [%1], 16;" :: "r"(sp), "l"(gptr));
}

// ---------------------------------------------------------------------------
// LayerNorm: one block per row, 256 threads, C=1024 (4 floats/thread)
// ---------------------------------------------------------------------------
__global__ __launch_bounds__(256)
void ln_kernel(const float* __restrict__ x, const float* __restrict__ g,
               const float* __restrict__ b, float* __restrict__ out) {
    __shared__ float rs[8];
    __shared__ float rq[8];
    const int row = blockIdx.x;
    const float* xr = x + (size_t)row * CC;
    float* yr = out + (size_t)row * CC;
    const int c = threadIdx.x * 4;

    float4 v = *(const float4*)(xr + c);
    float s  = v.x + v.y + v.z + v.w;
    float sq = v.x * v.x + v.y * v.y + v.z * v.z + v.w * v.w;
    #pragma unroll
    for (int o = 16; o; o >>= 1) {
        s  += __shfl_xor_sync(0xffffffffu, s, o);
        sq += __shfl_xor_sync(0xffffffffu, sq, o);
    }
    if ((threadIdx.x & 31) == 0) {
        rs[threadIdx.x >> 5] = s;
        rq[threadIdx.x >> 5] = sq;
    }
    __syncthreads();
    s = 0.f; sq = 0.f;
    #pragma unroll
    for (int i = 0; i < 8; i++) { s += rs[i]; sq += rq[i]; }

    const float mean = s * (1.f / CC);
    const float var  = sq * (1.f / CC) - mean * mean;
    const float rstd = rsqrtf(var + 1e-5f);

    float4 g4 = *(const float4*)(g + c);
    float4 b4 = *(const float4*)(b + c);
    float4 o;
    o.x = (v.x - mean) * rstd * g4.x + b4.x;
    o.y = (v.y - mean) * rstd * g4.y + b4.y;
    o.z = (v.z - mean) * rstd * g4.z + b4.z;
    o.w = (v.w - mean) * rstd * g4.w + b4.w;
    *(float4*)(yr + c) = o;
}

// ---------------------------------------------------------------------------
// TF32 tensor-core GEMM: C[M,N] = A[M,K] @ B[K,N] + bias (+Res | relu)
// 128x128 CTA tile, BK=16, cp.async double buffering, 8 warps (2x4),
// warp tile 64x32 via m16n8k8 tf32 mma (4 m-tiles x 4 n-tiles).
// Smem pads: A row stride 20 floats, B row stride 136 floats -> all
// fragment LDS patterns conflict-free.
// EPI: 0 = bias, 1 = bias + residual add, 2 = bias + relu
// ---------------------------------------------------------------------------
#define BKK 16

template <int EPI>
__global__ __launch_bounds__(256, 2)
void tgemm_kernel(const float* __restrict__ A, const float* __restrict__ B,
                  const float* __restrict__ bias, const float* __restrict__ Res,
                  float* __restrict__ C, int M, int N, int K) {
    __shared__ __align__(16) float As[2][128][20];
    __shared__ __align__(16) float Bs[2][BKK][136];

    const int tid  = threadIdx.x;
    const int warp = tid >> 5;
    const int lane = tid & 31;
    const int gid  = lane >> 2;   // 0..7
    const int tig  = lane & 3;    // 0..3
    const int wm   = (warp >> 2) * 64;   // warp m offset in tile
    const int wn   = (warp & 3) * 32;    // warp n offset in tile
    const int m0   = blockIdx.y * 128;
    const int n0   = blockIdx.x * 128;

    float acc[4][4][4];
    #pragma unroll
    for (int i = 0; i < 4; i++)
        #pragma unroll
        for (int j = 0; j < 4; j++)
            #pragma unroll
            for (int r = 0; r < 4; r++) acc[i][j][r] = 0.f;

    const int NIT = K / BKK;

    // tile loader: A 128x16 (512 float4), B 16x128 (512 float4); 2 each/thread
    auto load_tile = [&](int it, int buf) {
        const int kbase = it * BKK;
        #pragma unroll
        for (int s = 0; s < 2; s++) {
            const int seg = tid * 2 + s;          // 0..511
            const int r  = seg >> 2;              // 0..127
            const int kk = (seg & 3) << 2;        // 0,4,8,12
            cp_async16(&As[buf][r][kk], A + (size_t)(m0 + r) * K + kbase + kk);
        }
        #pragma unroll
        for (int s = 0; s < 2; s++) {
            const int seg = tid * 2 + s;
            const int r  = seg >> 5;              // 0..15
            const int nn = (seg & 31) << 2;       // 0..124
            cp_async16(&Bs[buf][r][nn], B + (size_t)(kbase + r) * N + n0 + nn);
        }
        asm volatile("cp.async.commit_group;");
    };

    load_tile(0, 0);

    for (int it = 0; it < NIT; it++) {
        const int buf = it & 1;
        if (it + 1 < NIT) {
            load_tile(it + 1, buf ^ 1);
            asm volatile("cp.async.wait_group 1;");
        } else {
            asm volatile("cp.async.wait_group 0;");
        }
        __syncthreads();

        #pragma unroll
        for (int ks = 0; ks < BKK / 8; ks++) {
            const int k0 = ks * 8;
            uint32_t af[4][4], bf[4][2];
            #pragma unroll
            for (int i = 0; i < 4; i++) {
                const int rb = wm + i * 16 + gid;
                af[i][0] = f2tf32(As[buf][rb    ][k0 + tig]);
                af[i][1] = f2tf32(As[buf][rb + 8][k0 + tig]);
                af[i][2] = f2tf32(As[buf][rb    ][k0 + tig + 4]);
                af[i][3] = f2tf32(As[buf][rb + 8][k0 + tig + 4]);
            }
            #pragma unroll
            for (int j = 0; j < 4; j++) {
                const int cb = wn + j * 8 + gid;
                bf[j][0] = f2tf32(Bs[buf][k0 + tig    ][cb]);
                bf[j][1] = f2tf32(Bs[buf][k0 + tig + 4][cb]);
            }
            #pragma unroll
            for (int i = 0; i < 4; i++)
                #pragma unroll
                for (int j = 0; j < 4; j++)
                    mma_tf32(acc[i][j], af[i], bf[j]);
        }
        __syncthreads();
    }

    // epilogue: c0/c1 at row gid, cols 2*tig,2*tig+1; c2/c3 at row gid+8
    #pragma unroll
    for (int i = 0; i < 4; i++) {
        #pragma unroll
        for (int half = 0; half < 2; half++) {
            const int r = m0 + wm + i * 16 + gid + half * 8;
            const size_t rowoff = (size_t)r * N;
            #pragma unroll
            for (int j = 0; j < 4; j++) {
                const int c = n0 + wn + j * 8 + tig * 2;
                float v0 = acc[i][j][half * 2 + 0] + bias[c];
                float v1 = acc[i][j][half * 2 + 1] + bias[c + 1];
                if (EPI == 1) {
                    float2 r2 = *(const float2*)(Res + rowoff + c);
                    v0 += r2.x; v1 += r2.y;
                }
                if (EPI == 2) {
                    v0 = fmaxf(v0, 0.f); v1 = fmaxf(v1, 0.f);
                }
                float2 o; o.x = v0; o.y = v1;
                *(float2*)(C + rowoff + c) = o;
            }
        }
    }
}

// ---------------------------------------------------------------------------
// Causal flash attention, fp32. Block = (q-tile 64, head, batch), 256 thr.
// ---------------------------------------------------------------------------
__global__ __launch_bounds__(256)
void attn_kernel(const float* __restrict__ qkv, float* __restrict__ y) {
    __shared__ __align__(16) float Qs[64][64];   // Q^T, pre-scaled
    __shared__ __align__(16) float KPs[64][64];  // K^T, then P^T
    __shared__ __align__(16) float Vs[64][64];   // V natural [c][d]

    const int tid = threadIdx.x;
    const int qb = blockIdx.x;
    const int h  = blockIdx.y;
    const int b  = blockIdx.z;
    const int rg = tid >> 4;
    const int cg = tid & 15;

    const size_t base = (size_t)b * TT * (3 * CC) + (size_t)h * DD;

    for (int i4 = tid; i4 < 1024; i4 += 256) {
        const int r = i4 >> 4;
        const int d0 = (i4 & 15) << 2;
        float4 q4 = *(const float4*)(qkv + base + (size_t)(qb * 64 + r) * (3 * CC) + d0);
        Qs[d0 + 0][r] = q4.x * SCALE_ATTN;
        Qs[d0 + 1][r] = q4.y * SCALE_ATTN;
        Qs[d0 + 2][r] = q4.z * SCALE_ATTN;
        Qs[d0 + 3][r] = q4.w * SCALE_ATTN;
    }

    float m[4], l[4], acc[4][4];
    #pragma unroll
    for (int i = 0; i < 4; i++) {
        m[i] = -1e30f; l[i] = 0.f;
        #pragma unroll
        for (int j = 0; j < 4; j++) acc[i][j] = 0.f;
    }

    for (int kb = 0; kb <= qb; kb++) {
        __syncthreads();
        for (int i4 = tid; i4 < 1024; i4 += 256) {
            const int c = i4 >> 4;
            const int d0 = (i4 & 15) << 2;
            const size_t kaddr = base + CC + (size_t)(kb * 64 + c) * (3 * CC) + d0;
            float4 k4 = *(const float4*)(qkv + kaddr);
            KPs[d0 + 0][c] = k4.x;
            KPs[d0 + 1][c] = k4.y;
            KPs[d0 + 2][c] = k4.z;
            KPs[d0 + 3][c] = k4.w;
            float4 v4 = *(const float4*)(qkv + kaddr + CC);
            *(float4*)&Vs[c][d0] = v4;
        }
        __syncthreads();

        float s[4][4];
        #pragma unroll
        for (int i = 0; i < 4; i++)
            #pragma unroll
            for (int j = 0; j < 4; j++) s[i][j] = 0.f;

        #pragma unroll 8
        for (int d = 0; d < 64; d++) {
            float qa[4], kk[4];
            *(float4*)qa = *(const float4*)&Qs[d][rg << 2];
            *(float4*)kk = *(const float4*)&KPs[d][cg << 2];
            #pragma unroll
            for (int i = 0; i < 4; i++)
                #pragma unroll
                for (int j = 0; j < 4; j++)
                    s[i][j] = fmaf(qa[i], kk[j], s[i][j]);
        }

        if (kb == qb) {
            #pragma unroll
            for (int i = 0; i < 4; i++)
                #pragma unroll
                for (int j = 0; j < 4; j++)
                    if ((cg << 2) + j > (rg << 2) + i) s[i][j] = -1e30f;
        }

        float rmax[4], rsum[4], corr[4];
        #pragma unroll
        for (int i = 0; i < 4; i++)
            rmax[i] = fmaxf(fmaxf(s[i][0], s[i][1]), fmaxf(s[i][2], s[i][3]));
        #pragma unroll
        for (int o = 1; o < 16; o <<= 1)
            #pragma unroll
            for (int i = 0; i < 4; i++)
                rmax[i] = fmaxf(rmax[i], __shfl_xor_sync(0xffffffffu, rmax[i], o));
        #pragma unroll
        for (int i = 0; i < 4; i++) {
            const float mn = fmaxf(m[i], rmax[i]);
            corr[i] = __expf(m[i] - mn);
            m[i] = mn;
            rsum[i] = 0.f;
            #pragma unroll
            for (int j = 0; j < 4; j++) {
                s[i][j] = __expf(s[i][j] - mn);
                rsum[i] += s[i][j];
            }
        }
        #pragma unroll
        for (int o = 1; o < 16; o <<= 1)
            #pragma unroll
            for (int i = 0; i < 4; i++)
                rsum[i] += __shfl_xor_sync(0xffffffffu, rsum[i], o);
        #pragma unroll
        for (int i = 0; i < 4; i++) {
            l[i] = l[i] * corr[i] + rsum[i];
            #pragma unroll
            for (int j = 0; j < 4; j++) acc[i][j] *= corr[i];
        }

        __syncthreads();
        #pragma unroll
        for (int j = 0; j < 4; j++) {
            const int c = (cg << 2) + j;
            *(float4*)&KPs[c][rg << 2] = make_float4(s[0][j], s[1][j], s[2][j], s[3][j]);
        }
        __syncthreads();

        #pragma unroll 8
        for (int c = 0; c < 64; c++) {
            float p[4], vv[4];
            *(float4*)p  = *(const float4*)&KPs[c][rg << 2];
            *(float4*)vv = *(const float4*)&Vs[c][cg << 2];
            #pragma unroll
            for (int i = 0; i < 4; i++)
                #pragma unroll
                for (int j = 0; j < 4; j++)
                    acc[i][j] = fmaf(p[i], vv[j], acc[i][j]);
        }
    }

    #pragma unroll
    for (int i = 0; i < 4; i++) {
        const float inv = 1.f / l[i];
        const int r = (rg << 2) + i;
        const size_t off = ((size_t)(b * TT + qb * 64 + r)) * CC + h * DD + (cg << 2);
        float4 o = make_float4(acc[i][0] * inv, acc[i][1] * inv,
                               acc[i][2] * inv, acc[i][3] * inv);
        *(float4*)(y + off) = o;
    }
}

// ---------------------------------------------------------------------------
// Launch
// ---------------------------------------------------------------------------
extern "C" void kernel_launch(void* const* d_in, const int* in_sizes, int n_in,
                              void* d_out, int out_size) {
    const float* x     = (const float*)d_in[0];
    const float* Wqkv  = (const float*)d_in[1];
    const float* bqkv  = (const float*)d_in[2];
    const float* Wproj = (const float*)d_in[3];
    const float* bproj = (const float*)d_in[4];
    const float* ln1_g = (const float*)d_in[5];
    const float* ln1_b = (const float*)d_in[6];
    const float* ln2_g = (const float*)d_in[7];
    const float* ln2_b = (const float*)d_in[8];
    const float* W1    = (const float*)d_in[9];
    const float* b1    = (const float*)d_in[10];
    const float* W2    = (const float*)d_in[11];
    const float* b2    = (const float*)d_in[12];
    float* out = (float*)d_out;

    float *h, *qkv, *y, *h2, *mid;
    cudaGetSymbolAddress((void**)&h,   g_h);
    cudaGetSymbolAddress((void**)&qkv, g_qkv);
    cudaGetSymbolAddress((void**)&y,   g_y);
    cudaGetSymbolAddress((void**)&h2,  g_h2);
    cudaGetSymbolAddress((void**)&mid, g_mid);

    // 1. h = ln1(x)
    ln_kernel<<<NTOK, 256>>>(x, ln1_g, ln1_b, h);
    // 2. qkv = h @ Wqkv + bqkv
    tgemm_kernel<0><<<dim3(3 * CC / 128, NTOK / 128), 256>>>(
        h, Wqkv, bqkv, nullptr, qkv, NTOK, 3 * CC, CC);
    // 3. y = causal_attention(qkv)
    attn_kernel<<<dim3(TT / 64, HH, BB), 256>>>(qkv, y);
    // 4. out = x + y @ Wproj + bproj    (x1 lives in d_out)
    tgemm_kernel<1><<<dim3(CC / 128, NTOK / 128), 256>>>(
        y, Wproj, bproj, x, out, NTOK, CC, CC);
    // 5. h2 = ln2(x1)
    ln_kernel<<<NTOK, 256>>>(out, ln2_g, ln2_b, h2);
    // 6. mid = relu(h2 @ W1 + b1)
    tgemm_kernel<2><<<dim3(4 * CC / 128, NTOK / 128), 256>>>(
        h2, W1, b1, nullptr, mid, NTOK, 4 * CC, CC);
    // 7. out = x1 + mid @ W2 + b2   (in-place residual on d_out)
    tgemm_kernel<1><<<dim3(CC / 128, NTOK / 128), 256>>>(
        mid, W2, b2, out, out, NTOK, CC, 4 * CC);
}